// round 15
// baseline (speedup 1.0000x reference)
#include <cuda_runtime.h>
#include <cstdint>
#include <cstddef>

// ---------------------------------------------------------------------------
// out = fq(x) @ fq(W)^T + bias, fq = per-tensor symmetric int8 fake quant.
// Exact: out = (q_x @ q_w^T) * (s_x*s_w) + bias, int32 accumulation.
//
// R13: FUSED hybrid CTA. Previous rounds split tensor/dp4a work across CTA
// types; ncu showed total time invariant to the split because tensor idles
// whenever an SM's 2 CTA slots both hold dp4a CTAs (busy = 1-p^2 = 81%).
// Now every CTA is 128x128 with intra-CTA warp specialization:
//   warps 0-3: IMMA (mma.m16n8k32) on cols [0,64)   -> tensor pipe
//   warps 4-7: dp4a SIMT           on cols [64,128) -> ALU pipe
// Every SM always has tensor work -> tensor ~100% busy; dp4a (~1.0ms of
// rt~1 ALU slots per SM for its 2048 cols) hides under the 1.77ms tensor time.
// ---------------------------------------------------------------------------

#define MT 16384
#define NT 4096
#define KT 4096

__device__ __align__(1024) int8_t g_qx[(size_t)MT * KT]; // 64 MiB scratch
__device__ __align__(1024) int8_t g_qw[(size_t)NT * KT]; // 16 MiB scratch
__device__ unsigned g_amax_x;
__device__ unsigned g_amax_w;

__device__ __forceinline__ uint32_t smem_to_u32(const void* smem_ptr) {
    uint32_t addr;
    asm("{ .reg .u64 tmp; cvta.to.shared.u64 tmp, %1; cvt.u32.u64 %0, tmp; }"
        : "=r"(addr) : "l"(smem_ptr));
    return addr;
}

// ---------------------------------------------------------------------------
// Pass 0: reset reduction state
// ---------------------------------------------------------------------------
__global__ void init_kernel() {
    if (threadIdx.x == 0) { g_amax_x = 0u; g_amax_w = 0u; }
}

// ---------------------------------------------------------------------------
// Pass 1 (fused): abs-max of x (blocks [0,XB)) and w (blocks [XB,XB+WB))
// ---------------------------------------------------------------------------
#define XB 2048
#define WB 512
__global__ void amax_fused_kernel(const float* __restrict__ x,
                                  const float* __restrict__ w) {
    __shared__ float red[8];
    int isw = (blockIdx.x >= XB);
    const float4* p4 = (const float4*)(isw ? w : x);
    int n4 = isw ? (NT * KT / 4) : (MT * KT / 4);
    int nb = isw ? WB : XB;
    int bid = isw ? (blockIdx.x - XB) : blockIdx.x;

    float m = 0.f;
    int stride = nb * blockDim.x;
    for (int i = bid * blockDim.x + threadIdx.x; i < n4; i += stride) {
        float4 v = p4[i];
        m = fmaxf(m, fmaxf(fmaxf(fabsf(v.x), fabsf(v.y)),
                           fmaxf(fabsf(v.z), fabsf(v.w))));
    }
    #pragma unroll
    for (int o = 16; o; o >>= 1) m = fmaxf(m, __shfl_xor_sync(0xffffffffu, m, o));
    if ((threadIdx.x & 31) == 0) red[threadIdx.x >> 5] = m;
    __syncthreads();
    if (threadIdx.x == 0) {
        float mm = red[0];
        for (int j = 1; j < (int)(blockDim.x >> 5); j++) mm = fmaxf(mm, red[j]);
        atomicMax(isw ? &g_amax_w : &g_amax_x, __float_as_uint(mm));
    }
}

// ---------------------------------------------------------------------------
// Pass 2 (fused): quantize x and w to int8
// ---------------------------------------------------------------------------
#define QXB 4096
#define QWB 1024
__device__ __forceinline__ int q1(float v, float inv_scale) {
    int q = __float2int_rn(v * inv_scale);   // round-half-even like jnp.round
    return max(-127, min(127, q));
}

__global__ void quant_fused_kernel(const float* __restrict__ x,
                                   const float* __restrict__ w) {
    int isw = (blockIdx.x >= QXB);
    float scale = fmaxf(__uint_as_float(isw ? g_amax_w : g_amax_x) * (1.f / 127.f),
                        1e-8f);
    float inv = 1.f / scale;
    const float4* in4 = (const float4*)(isw ? w : x);
    uint32_t* o4 = isw ? (uint32_t*)g_qw : (uint32_t*)g_qx;
    int n4 = isw ? (NT * KT / 4) : (MT * KT / 4);
    int nb = isw ? QWB : QXB;
    int bid = isw ? (blockIdx.x - QXB) : blockIdx.x;

    int stride = nb * blockDim.x;
    for (int i = bid * blockDim.x + threadIdx.x; i < n4; i += stride) {
        float4 v = in4[i];
        uint32_t u = (uint32_t)(q1(v.x, inv) & 0xff)
                   | ((uint32_t)(q1(v.y, inv) & 0xff) << 8)
                   | ((uint32_t)(q1(v.z, inv) & 0xff) << 16)
                   | ((uint32_t)(q1(v.w, inv) & 0xff) << 24);
        o4[i] = u;
    }
}

// ---------------------------------------------------------------------------
// Pass 3: fused-hybrid GEMM. Tile 128x128x128, 256 threads, 3-stage cp.async.
//   smem stage: A[128x128] swz128 | B_imma[64x128] swz128 | B_dp[64x128] swzdp
// ---------------------------------------------------------------------------
#define BM 128
#define BK 128
#define STAGES 3
#define NITER (KT / BK)                  // 32
#define ASZ (BM * BK)                    // 16384 B
#define BSZI (64 * BK)                   // 8192 B
#define BSZD (64 * BK)                   // 8192 B
#define STAGE_BYTES (ASZ + BSZI + BSZD)  // 32768 B
#define GEMM_SMEM (STAGES * STAGE_BYTES) // 98304 B

// ldmatrix-compatible swizzle: 128B rows, chunk' = chunk ^ (row&7)
__device__ __forceinline__ uint32_t swz128(uint32_t row, uint32_t c) {
    return row * 128u + ((c ^ (row & 7u)) << 4);
}
// dp4a B swizzle: chunk' = chunk ^ ((row ^ row>>3)&7)
__device__ __forceinline__ uint32_t swzdp(uint32_t row, uint32_t c) {
    return row * 128u + ((c ^ ((row ^ (row >> 3)) & 7u)) << 4);
}

#define CP16(dst, src) \
    asm volatile("cp.async.cg.shared.global [%0], [%1], 16;" :: "r"(dst), "l"(src))
#define CP_COMMIT() asm volatile("cp.async.commit_group;" ::: "memory")
#define CP_WAIT(n)  asm volatile("cp.async.wait_group %0;" :: "n"(n) : "memory")

#define LDSM_X4(r0, r1, r2, r3, a) \
    asm volatile("ldmatrix.sync.aligned.m8n8.x4.shared.b16 {%0,%1,%2,%3}, [%4];" \
        : "=r"(r0), "=r"(r1), "=r"(r2), "=r"(r3) : "r"(a))

#define MMA_S8(c, a, b0, b1) \
    asm volatile("mma.sync.aligned.m16n8k32.row.col.s32.s8.s8.s32 " \
        "{%0,%1,%2,%3}, {%4,%5,%6,%7}, {%8,%9}, {%0,%1,%2,%3};" \
        : "+r"((c)[0]), "+r"((c)[1]), "+r"((c)[2]), "+r"((c)[3]) \
        : "r"((a)[0]), "r"((a)[1]), "r"((a)[2]), "r"((a)[3]), "r"(b0), "r"(b1))

__global__ void __launch_bounds__(256, 2)
gemm_kernel(float* __restrict__ out, const float* __restrict__ bias) {
    extern __shared__ char smem[];
    uint32_t sb = smem_to_u32(smem);
    int tid = threadIdx.x, lane = tid & 31, w = tid >> 5;
    int mtile = blockIdx.y;
    int ncol0 = blockIdx.x * 128;

    // Loader mapping (all 256 threads): r0 in 0..31, chunk cc in 0..7.
    int r0 = tid >> 3, cc = tid & 7;
    const int8_t* gA  = g_qx + ((size_t)(mtile * BM + r0)) * KT + cc * 16;
    const int8_t* gBi = g_qw + ((size_t)(ncol0 + r0)) * KT + cc * 16;
    const int8_t* gBd = g_qw + ((size_t)(ncol0 + 64 + r0)) * KT + cc * 16;
    uint32_t dA  = swz128((uint32_t)r0, (uint32_t)cc);
    uint32_t dBi0 = swz128((uint32_t)r0, (uint32_t)cc);
    uint32_t dBi1 = swz128((uint32_t)(r0 + 32), (uint32_t)cc);
    uint32_t dBd0 = swzdp((uint32_t)r0, (uint32_t)cc);
    uint32_t dBd1 = swzdp((uint32_t)(r0 + 32), (uint32_t)cc);

    float sx = fmaxf(__uint_as_float(g_amax_x) * (1.f / 127.f), 1e-8f);
    float sw = fmaxf(__uint_as_float(g_amax_w) * (1.f / 127.f), 1e-8f);
    float sc = sx * sw;

    // Prologue loads: stages 0..STAGES-2
    #pragma unroll
    for (int s = 0; s < STAGES - 1; s++) {
        uint32_t st = sb + (uint32_t)s * STAGE_BYTES;
        #pragma unroll
        for (int it = 0; it < 4; it++)
            CP16(st + dA + it * 4096u, gA + (size_t)it * 32 * KT + s * BK);
        CP16(st + ASZ + dBi0, gBi + s * BK);
        CP16(st + ASZ + dBi1, gBi + (size_t)32 * KT + s * BK);
        CP16(st + ASZ + BSZI + dBd0, gBd + s * BK);
        CP16(st + ASZ + BSZI + dBd1, gBd + (size_t)32 * KT + s * BK);
        CP_COMMIT();
    }

    if (w < 4) {
        // ============ IMMA warps: cols [ncol0, ncol0+64) ====================
        int wm = w & 1, wn = w >> 1;      // 2x2 warp grid over 128x64
        int acc[4][4][4];
        #pragma unroll
        for (int i = 0; i < 4; i++)
            #pragma unroll
            for (int j = 0; j < 4; j++)
                #pragma unroll
                for (int k = 0; k < 4; k++) acc[i][j][k] = 0;

        uint32_t a_row = (uint32_t)(wm * 64 + ((lane >> 3) & 1) * 8 + (lane & 7));
        uint32_t a_cb  = (uint32_t)((lane >> 4) & 1);
        uint32_t aoff[4];
        #pragma unroll
        for (int mt = 0; mt < 4; mt++) aoff[mt] = swz128(a_row + mt * 16, a_cb);

        uint32_t b_row = (uint32_t)(wn * 32 + ((lane >> 4) & 1) * 8 + (lane & 7));
        uint32_t b_cb  = (uint32_t)((lane >> 3) & 1);
        uint32_t boff[2];
        #pragma unroll
        for (int p = 0; p < 2; p++) boff[p] = swz128(b_row + p * 16, b_cb);

        uint32_t afr[2][4][4], bfr[2][2][4];

        for (int kc = 0; kc < NITER; kc++) {
            CP_WAIT(STAGES - 2);
            __syncthreads();

            int lc = kc + STAGES - 1;
            if (lc < NITER) {
                uint32_t st = sb + (uint32_t)(lc % STAGES) * STAGE_BYTES;
                #pragma unroll
                for (int it = 0; it < 4; it++)
                    CP16(st + dA + it * 4096u, gA + (size_t)it * 32 * KT + lc * BK);
                CP16(st + ASZ + dBi0, gBi + lc * BK);
                CP16(st + ASZ + dBi1, gBi + (size_t)32 * KT + lc * BK);
                CP16(st + ASZ + BSZI + dBd0, gBd + lc * BK);
                CP16(st + ASZ + BSZI + dBd1, gBd + (size_t)32 * KT + lc * BK);
            }
            CP_COMMIT();

            uint32_t sA = sb + (uint32_t)(kc % STAGES) * STAGE_BYTES;
            uint32_t sB = sA + ASZ;

            #pragma unroll
            for (int mt = 0; mt < 4; mt++)
                LDSM_X4(afr[0][mt][0], afr[0][mt][1], afr[0][mt][2], afr[0][mt][3],
                        sA + aoff[mt]);
            #pragma unroll
            for (int p = 0; p < 2; p++)
                LDSM_X4(bfr[0][p][0], bfr[0][p][1], bfr[0][p][2], bfr[0][p][3],
                        sB + boff[p]);

            #pragma unroll
            for (int ks = 0; ks < 4; ks++) {
                int cur = ks & 1, nxt = cur ^ 1;
                if (ks < 3) {
                    uint32_t x = (uint32_t)(ks + 1) << 5;
                    #pragma unroll
                    for (int mt = 0; mt < 4; mt++)
                        LDSM_X4(afr[nxt][mt][0], afr[nxt][mt][1],
                                afr[nxt][mt][2], afr[nxt][mt][3],
                                sA + (aoff[mt] ^ x));
                    #pragma unroll
                    for (int p = 0; p < 2; p++)
                        LDSM_X4(bfr[nxt][p][0], bfr[nxt][p][1],
                                bfr[nxt][p][2], bfr[nxt][p][3],
                                sB + (boff[p] ^ x));
                }
                #pragma unroll
                for (int mt = 0; mt < 4; mt++)
                    #pragma unroll
                    for (int nt = 0; nt < 4; nt++)
                        MMA_S8(acc[mt][nt], afr[cur][mt],
                               bfr[cur][nt >> 1][(nt & 1) * 2],
                               bfr[cur][nt >> 1][(nt & 1) * 2 + 1]);
            }
        }

        int colbase = ncol0 + wn * 32 + 2 * (lane & 3);
        int rowbase = mtile * BM + wm * 64 + (lane >> 2);

        float2 bv[4];
        #pragma unroll
        for (int nt = 0; nt < 4; nt++)
            bv[nt] = *reinterpret_cast<const float2*>(bias + colbase + nt * 8);

        #pragma unroll
        for (int mt = 0; mt < 4; mt++) {
            int r = rowbase + mt * 16;
            #pragma unroll
            for (int nt = 0; nt < 4; nt++) {
                int col = colbase + nt * 8;
                float2 v0, v1;
                v0.x = fmaf((float)acc[mt][nt][0], sc, bv[nt].x);
                v0.y = fmaf((float)acc[mt][nt][1], sc, bv[nt].y);
                v1.x = fmaf((float)acc[mt][nt][2], sc, bv[nt].x);
                v1.y = fmaf((float)acc[mt][nt][3], sc, bv[nt].y);
                *reinterpret_cast<float2*>(out + (size_t)r * NT + col) = v0;
                *reinterpret_cast<float2*>(out + (size_t)(r + 8) * NT + col) = v1;
            }
        }
    } else {
        // ============ dp4a warps: cols [ncol0+64, ncol0+128) ================
        int wgt = tid & 127;               // 0..127
        int ty = wgt >> 3;                 // 0..15
        int tx = wgt & 7;                  // 0..7
        // Thread outputs: rows ty+16*i (i 0..7)  x  cols 64+8*tx+j (j 0..7).
        // Lane-adjacent ty -> distinct swz128 phases -> conflict-free A reads.
        uint32_t abase[8], bbase[8];
        #pragma unroll
        for (int i = 0; i < 8; i++)
            abase[i] = (uint32_t)(ty + 16 * i) * 128u + ((uint32_t)(ty & 7) << 4);
        #pragma unroll
        for (int j = 0; j < 8; j++)
            bbase[j] = (uint32_t)(tx * 8 + j) * 128u
                     + ((uint32_t)((j ^ tx) & 7) << 4);

        int acc[8][8];
        #pragma unroll
        for (int i = 0; i < 8; i++)
            #pragma unroll
            for (int j = 0; j < 8; j++) acc[i][j] = 0;

        for (int kc = 0; kc < NITER; kc++) {
            CP_WAIT(STAGES - 2);
            __syncthreads();

            int lc = kc + STAGES - 1;
            if (lc < NITER) {
                uint32_t st = sb + (uint32_t)(lc % STAGES) * STAGE_BYTES;
                #pragma unroll
                for (int it = 0; it < 4; it++)
                    CP16(st + dA + it * 4096u, gA + (size_t)it * 32 * KT + lc * BK);
                CP16(st + ASZ + dBi0, gBi + lc * BK);
                CP16(st + ASZ + dBi1, gBi + (size_t)32 * KT + lc * BK);
                CP16(st + ASZ + BSZI + dBd0, gBd + lc * BK);
                CP16(st + ASZ + BSZI + dBd1, gBd + (size_t)32 * KT + lc * BK);
            }
            CP_COMMIT();

            const char* base = smem + (size_t)(kc % STAGES) * STAGE_BYTES;
            const char* bdp = base + ASZ + BSZI;

            #pragma unroll
            for (int c = 0; c < 8; c++) {
                uint32_t cx = (uint32_t)c << 4;
                #pragma unroll
                for (int h = 0; h < 2; h++) {
                    uint2 a2[8];
                    #pragma unroll
                    for (int i = 0; i < 8; i++)
                        a2[i] = *(const uint2*)(base + ((abase[i] ^ cx) + 8 * h));
                    #pragma unroll
                    for (int j = 0; j < 8; j++) {
                        uint2 b2 = *(const uint2*)(bdp + ((bbase[j] ^ cx) + 8 * h));
                        #pragma unroll
                        for (int i = 0; i < 8; i++) {
                            acc[i][j] = __dp4a((int)a2[i].x, (int)b2.x, acc[i][j]);
                            acc[i][j] = __dp4a((int)a2[i].y, (int)b2.y, acc[i][j]);
                        }
                    }
                }
            }
        }

        // epilogue: rows ty+16i, cols ncol0+64+8tx..+7
        int gcol = ncol0 + 64 + tx * 8;
        float4 bv0 = *reinterpret_cast<const float4*>(bias + gcol);
        float4 bv1 = *reinterpret_cast<const float4*>(bias + gcol + 4);
        #pragma unroll
        for (int i = 0; i < 8; i++) {
            int grow = mtile * BM + ty + 16 * i;
            float* orow = out + (size_t)grow * NT + gcol;
            float4 v0, v1;
            v0.x = fmaf((float)acc[i][0], sc, bv0.x);
            v0.y = fmaf((float)acc[i][1], sc, bv0.y);
            v0.z = fmaf((float)acc[i][2], sc, bv0.z);
            v0.w = fmaf((float)acc[i][3], sc, bv0.w);
            v1.x = fmaf((float)acc[i][4], sc, bv1.x);
            v1.y = fmaf((float)acc[i][5], sc, bv1.y);
            v1.z = fmaf((float)acc[i][6], sc, bv1.z);
            v1.w = fmaf((float)acc[i][7], sc, bv1.w);
            *reinterpret_cast<float4*>(orow) = v0;
            *reinterpret_cast<float4*>(orow + 4) = v1;
        }
    }
}

// ---------------------------------------------------------------------------
// Launch (graph-capturable; no allocation, no sync)
// ---------------------------------------------------------------------------
extern "C" void kernel_launch(void* const* d_in, const int* in_sizes, int n_in,
                              void* d_out, int out_size) {
    const float* x = (const float*)d_in[0];
    const float* w = (const float*)d_in[1];
    const float* bias = (const float*)d_in[2];
    float* out = (float*)d_out;

    init_kernel<<<1, 32>>>();
    amax_fused_kernel<<<XB + WB, 256>>>(x, w);
    quant_fused_kernel<<<QXB + QWB, 256>>>(x, w);

    cudaFuncSetAttribute(gemm_kernel,
                         cudaFuncAttributeMaxDynamicSharedMemorySize, GEMM_SMEM);
    gemm_kernel<<<dim3(NT / 128, MT / BM), 256, GEMM_SMEM>>>(out, bias);
}

// round 16
// speedup vs baseline: 1.0096x; 1.0096x over previous
#include <cuda_runtime.h>
#include <cstdint>
#include <cstddef>

// ---------------------------------------------------------------------------
// out = fq(x) @ fq(W)^T + bias, fq = per-tensor symmetric int8 fake quant.
// Exact: out = (q_x @ q_w^T) * (s_x*s_w) + bias, int32 accumulation.
//
// R15: fused hybrid, rebalanced + interleaved. Every CTA computes a 128x128
// tile; EVERY warp does both IMMA (cols [0,96), 4x2 warp grid, 48 MMA/kc)
// and dp4a (cols [96,128), 16 outputs/thread, 512 dp4a/thread/kc).
// Per-SMSP/kc: tensor 11.5K cyc (binding), dp4a pipe 4.1K (hidden), issue 25%.
// No CTA pairing randomness (R7-R11 flaw), no inter-warp imbalance (R13 flaw).
// ---------------------------------------------------------------------------

#define MT 16384
#define NT 4096
#define KT 4096

__device__ __align__(1024) int8_t g_qx[(size_t)MT * KT]; // 64 MiB scratch
__device__ __align__(1024) int8_t g_qw[(size_t)NT * KT]; // 16 MiB scratch
__device__ unsigned g_amax_x;
__device__ unsigned g_amax_w;

__device__ __forceinline__ uint32_t smem_to_u32(const void* smem_ptr) {
    uint32_t addr;
    asm("{ .reg .u64 tmp; cvta.to.shared.u64 tmp, %1; cvt.u32.u64 %0, tmp; }"
        : "=r"(addr) : "l"(smem_ptr));
    return addr;
}

// ---------------------------------------------------------------------------
// Pass 0: reset reduction state
// ---------------------------------------------------------------------------
__global__ void init_kernel() {
    if (threadIdx.x == 0) { g_amax_x = 0u; g_amax_w = 0u; }
}

// ---------------------------------------------------------------------------
// Pass 1 (fused): abs-max of x (blocks [0,XB)) and w (blocks [XB,XB+WB))
// ---------------------------------------------------------------------------
#define XB 2048
#define WB 512
__global__ void amax_fused_kernel(const float* __restrict__ x,
                                  const float* __restrict__ w) {
    __shared__ float red[8];
    int isw = (blockIdx.x >= XB);
    const float4* p4 = (const float4*)(isw ? w : x);
    int n4 = isw ? (NT * KT / 4) : (MT * KT / 4);
    int nb = isw ? WB : XB;
    int bid = isw ? (blockIdx.x - XB) : blockIdx.x;

    float m = 0.f;
    int stride = nb * blockDim.x;
    for (int i = bid * blockDim.x + threadIdx.x; i < n4; i += stride) {
        float4 v = p4[i];
        m = fmaxf(m, fmaxf(fmaxf(fabsf(v.x), fabsf(v.y)),
                           fmaxf(fabsf(v.z), fabsf(v.w))));
    }
    #pragma unroll
    for (int o = 16; o; o >>= 1) m = fmaxf(m, __shfl_xor_sync(0xffffffffu, m, o));
    if ((threadIdx.x & 31) == 0) red[threadIdx.x >> 5] = m;
    __syncthreads();
    if (threadIdx.x == 0) {
        float mm = red[0];
        for (int j = 1; j < (int)(blockDim.x >> 5); j++) mm = fmaxf(mm, red[j]);
        atomicMax(isw ? &g_amax_w : &g_amax_x, __float_as_uint(mm));
    }
}

// ---------------------------------------------------------------------------
// Pass 2 (fused): quantize x and w to int8
// ---------------------------------------------------------------------------
#define QXB 4096
#define QWB 1024
__device__ __forceinline__ int q1(float v, float inv_scale) {
    int q = __float2int_rn(v * inv_scale);   // round-half-even like jnp.round
    return max(-127, min(127, q));
}

__global__ void quant_fused_kernel(const float* __restrict__ x,
                                   const float* __restrict__ w) {
    int isw = (blockIdx.x >= QXB);
    float scale = fmaxf(__uint_as_float(isw ? g_amax_w : g_amax_x) * (1.f / 127.f),
                        1e-8f);
    float inv = 1.f / scale;
    const float4* in4 = (const float4*)(isw ? w : x);
    uint32_t* o4 = isw ? (uint32_t*)g_qw : (uint32_t*)g_qx;
    int n4 = isw ? (NT * KT / 4) : (MT * KT / 4);
    int nb = isw ? QWB : QXB;
    int bid = isw ? (blockIdx.x - QXB) : blockIdx.x;

    int stride = nb * blockDim.x;
    for (int i = bid * blockDim.x + threadIdx.x; i < n4; i += stride) {
        float4 v = in4[i];
        uint32_t u = (uint32_t)(q1(v.x, inv) & 0xff)
                   | ((uint32_t)(q1(v.y, inv) & 0xff) << 8)
                   | ((uint32_t)(q1(v.z, inv) & 0xff) << 16)
                   | ((uint32_t)(q1(v.w, inv) & 0xff) << 24);
        o4[i] = u;
    }
}

// ---------------------------------------------------------------------------
// Pass 3: fused-hybrid GEMM. Tile 128x128x128, 256 threads, 3-stage cp.async.
//   stage: A[128x128B] swz128 | B_imma[96x128B] swz128 | B_dp[32x128B] swzcol
// ---------------------------------------------------------------------------
#define BM 128
#define BK 128
#define STAGES 3
#define NITER (KT / BK)                  // 32
#define ASZ (BM * BK)                    // 16384 B
#define BSZI (96 * BK)                   // 12288 B
#define BSZD (32 * BK)                   // 4096 B
#define STAGE_BYTES (ASZ + BSZI + BSZD)  // 32768 B
#define GEMM_SMEM (STAGES * STAGE_BYTES) // 98304 B

// ldmatrix-compatible swizzle: 128B rows, chunk' = chunk ^ (row&7)
__device__ __forceinline__ uint32_t swz128(uint32_t row, uint32_t c) {
    return row * 128u + ((c ^ (row & 7u)) << 4);
}

#define CP16(dst, src) \
    asm volatile("cp.async.cg.shared.global [%0], [%1], 16;" :: "r"(dst), "l"(src))
#define CP_COMMIT() asm volatile("cp.async.commit_group;" ::: "memory")
#define CP_WAIT(n)  asm volatile("cp.async.wait_group %0;" :: "n"(n) : "memory")

#define LDSM_X4(r0, r1, r2, r3, a) \
    asm volatile("ldmatrix.sync.aligned.m8n8.x4.shared.b16 {%0,%1,%2,%3}, [%4];" \
        : "=r"(r0), "=r"(r1), "=r"(r2), "=r"(r3) : "r"(a))

#define MMA_S8(c, a, b0, b1) \
    asm volatile("mma.sync.aligned.m16n8k32.row.col.s32.s8.s8.s32 " \
        "{%0,%1,%2,%3}, {%4,%5,%6,%7}, {%8,%9}, {%0,%1,%2,%3};" \
        : "+r"((c)[0]), "+r"((c)[1]), "+r"((c)[2]), "+r"((c)[3]) \
        : "r"((a)[0]), "r"((a)[1]), "r"((a)[2]), "r"((a)[3]), "r"(b0), "r"(b1))

__global__ void __launch_bounds__(256, 2)
gemm_kernel(float* __restrict__ out, const float* __restrict__ bias) {
    extern __shared__ char smem[];
    uint32_t sb = smem_to_u32(smem);
    int tid = threadIdx.x, lane = tid & 31, w = tid >> 5;
    int mtile = blockIdx.y;
    int ncol0 = blockIdx.x * 128;

    // ---- loader mapping (all 256 threads): r0 in 0..31, chunk cc in 0..7 ---
    int r0 = tid >> 3, cc = tid & 7;
    const int8_t* gA  = g_qx + ((size_t)(mtile * BM + r0)) * KT + cc * 16;
    const int8_t* gBi = g_qw + ((size_t)(ncol0 + r0)) * KT + cc * 16;
    const int8_t* gBd = g_qw + ((size_t)(ncol0 + 96 + r0)) * KT + cc * 16;
    uint32_t dA  = swz128((uint32_t)r0, (uint32_t)cc);   // also valid +32it rows
    uint32_t phr = (uint32_t)((r0 ^ (r0 >> 2)) & 7);
    uint32_t dBd = (uint32_t)(ASZ + BSZI) + (uint32_t)r0 * 128u
                 + (((uint32_t)cc ^ phr) << 4);

    float sx = fmaxf(__uint_as_float(g_amax_x) * (1.f / 127.f), 1e-8f);
    float sw = fmaxf(__uint_as_float(g_amax_w) * (1.f / 127.f), 1e-8f);
    float sc = sx * sw;

    // ---- IMMA role: 4x2 warp grid over 128x96 ------------------------------
    int wm = w & 3, wn = w >> 2;       // wm rows*32, wn cols*48
    uint32_t a_row = (uint32_t)(wm * 32 + ((lane >> 3) & 1) * 8 + (lane & 7));
    uint32_t a_cb  = (uint32_t)((lane >> 4) & 1);
    uint32_t aoff[2];
    #pragma unroll
    for (int mt = 0; mt < 2; mt++) aoff[mt] = swz128(a_row + mt * 16, a_cb);

    uint32_t b_row = (uint32_t)(wn * 48 + ((lane >> 4) & 1) * 8 + (lane & 7));
    uint32_t b_cb  = (uint32_t)((lane >> 3) & 1);
    uint32_t boff[3];
    #pragma unroll
    for (int p = 0; p < 3; p++) boff[p] = swz128(b_row + p * 16, b_cb);

    int acc[2][6][4];
    #pragma unroll
    for (int i = 0; i < 2; i++)
        #pragma unroll
        for (int j = 0; j < 6; j++)
            #pragma unroll
            for (int k = 0; k < 4; k++) acc[i][j][k] = 0;

    // ---- dp4a role: thread tile 4 rows (stride 32) x 4 cols ---------------
    // rows: r0 + 32i; cols: 96 + cc*4 + j.  A reads reuse swz128 A tile
    // (rows 32 apart share phase r0&7 -> 4 distinct phases per warp).
    uint32_t abase[4];
    #pragma unroll
    for (int i = 0; i < 4; i++)
        abase[i] = (uint32_t)(r0 + 32 * i) * 128u + (((uint32_t)r0 & 7u) << 4);
    uint32_t bbase[4];
    #pragma unroll
    for (int j = 0; j < 4; j++) {
        uint32_t col = (uint32_t)(cc * 4 + j);
        uint32_t ph = (col ^ (col >> 2)) & 7u;
        bbase[j] = (uint32_t)(ASZ + BSZI) + col * 128u + (ph << 4);
    }
    int acc_d[4][4];
    #pragma unroll
    for (int i = 0; i < 4; i++)
        #pragma unroll
        for (int j = 0; j < 4; j++) acc_d[i][j] = 0;

    // ---- prologue: stages 0..STAGES-2 -------------------------------------
    #pragma unroll
    for (int s = 0; s < STAGES - 1; s++) {
        uint32_t st = sb + (uint32_t)s * STAGE_BYTES;
        #pragma unroll
        for (int it = 0; it < 4; it++)
            CP16(st + dA + it * 4096u, gA + (size_t)it * 32 * KT + s * BK);
        #pragma unroll
        for (int it = 0; it < 3; it++)
            CP16(st + ASZ + dA + it * 4096u, gBi + (size_t)it * 32 * KT + s * BK);
        CP16(st + dBd, gBd + s * BK);
        CP_COMMIT();
    }

    for (int kc = 0; kc < NITER; kc++) {
        CP_WAIT(STAGES - 2);
        __syncthreads();

        int lc = kc + STAGES - 1;
        if (lc < NITER) {
            uint32_t st = sb + (uint32_t)(lc % STAGES) * STAGE_BYTES;
            #pragma unroll
            for (int it = 0; it < 4; it++)
                CP16(st + dA + it * 4096u, gA + (size_t)it * 32 * KT + lc * BK);
            #pragma unroll
            for (int it = 0; it < 3; it++)
                CP16(st + ASZ + dA + it * 4096u,
                     gBi + (size_t)it * 32 * KT + lc * BK);
            CP16(st + dBd, gBd + lc * BK);
        }
        CP_COMMIT();

        uint32_t sA = sb + (uint32_t)(kc % STAGES) * STAGE_BYTES;
        uint32_t sB = sA + ASZ;

        // ---- IMMA section: 4 ks steps x 12 MMAs ---------------------------
        #pragma unroll
        for (int ks = 0; ks < 4; ks++) {
            uint32_t x = (uint32_t)ks << 5;
            uint32_t afr[2][4], bfr[3][4];
            #pragma unroll
            for (int mt = 0; mt < 2; mt++)
                LDSM_X4(afr[mt][0], afr[mt][1], afr[mt][2], afr[mt][3],
                        sA + (aoff[mt] ^ x));
            #pragma unroll
            for (int p = 0; p < 3; p++)
                LDSM_X4(bfr[p][0], bfr[p][1], bfr[p][2], bfr[p][3],
                        sB + (boff[p] ^ x));
            #pragma unroll
            for (int mt = 0; mt < 2; mt++)
                #pragma unroll
                for (int nt = 0; nt < 6; nt++)
                    MMA_S8(acc[mt][nt], afr[mt],
                           bfr[nt >> 1][(nt & 1) * 2],
                           bfr[nt >> 1][(nt & 1) * 2 + 1]);
        }

        // ---- dp4a section: cols [96,128) ----------------------------------
        const char* pst = smem + (size_t)(kc % STAGES) * STAGE_BYTES;
        #pragma unroll
        for (int c = 0; c < 8; c++) {
            uint32_t cx = (uint32_t)c << 4;
            uint4 a4[4];
            #pragma unroll
            for (int i = 0; i < 4; i++)
                a4[i] = *(const uint4*)(pst + (abase[i] ^ cx));
            #pragma unroll
            for (int j = 0; j < 4; j++) {
                uint4 b4 = *(const uint4*)(pst + (bbase[j] ^ cx));
                #pragma unroll
                for (int i = 0; i < 4; i++) {
                    acc_d[i][j] = __dp4a((int)a4[i].x, (int)b4.x, acc_d[i][j]);
                    acc_d[i][j] = __dp4a((int)a4[i].y, (int)b4.y, acc_d[i][j]);
                    acc_d[i][j] = __dp4a((int)a4[i].z, (int)b4.z, acc_d[i][j]);
                    acc_d[i][j] = __dp4a((int)a4[i].w, (int)b4.w, acc_d[i][j]);
                }
            }
        }
    }

    // ---- IMMA epilogue: cols [ncol0, ncol0+96) ----------------------------
    {
        int colbase = ncol0 + wn * 48 + 2 * (lane & 3);
        int rowbase = mtile * BM + wm * 32 + (lane >> 2);
        float2 bv[6];
        #pragma unroll
        for (int nt = 0; nt < 6; nt++)
            bv[nt] = *reinterpret_cast<const float2*>(bias + colbase + nt * 8);
        #pragma unroll
        for (int mt = 0; mt < 2; mt++) {
            int r = rowbase + mt * 16;
            #pragma unroll
            for (int nt = 0; nt < 6; nt++) {
                int col = colbase + nt * 8;
                float2 v0, v1;
                v0.x = fmaf((float)acc[mt][nt][0], sc, bv[nt].x);
                v0.y = fmaf((float)acc[mt][nt][1], sc, bv[nt].y);
                v1.x = fmaf((float)acc[mt][nt][2], sc, bv[nt].x);
                v1.y = fmaf((float)acc[mt][nt][3], sc, bv[nt].y);
                *reinterpret_cast<float2*>(out + (size_t)r * NT + col) = v0;
                *reinterpret_cast<float2*>(out + (size_t)(r + 8) * NT + col) = v1;
            }
        }
    }

    // ---- dp4a epilogue: cols [ncol0+96, ncol0+128) ------------------------
    {
        int gcol = ncol0 + 96 + cc * 4;
        float4 bv = *reinterpret_cast<const float4*>(bias + gcol);
        #pragma unroll
        for (int i = 0; i < 4; i++) {
            int grow = mtile * BM + r0 + 32 * i;
            float4 v;
            v.x = fmaf((float)acc_d[i][0], sc, bv.x);
            v.y = fmaf((float)acc_d[i][1], sc, bv.y);
            v.z = fmaf((float)acc_d[i][2], sc, bv.z);
            v.w = fmaf((float)acc_d[i][3], sc, bv.w);
            *reinterpret_cast<float4*>(out + (size_t)grow * NT + gcol) = v;
        }
    }
}

// ---------------------------------------------------------------------------
// Launch (graph-capturable; no allocation, no sync)
// ---------------------------------------------------------------------------
extern "C" void kernel_launch(void* const* d_in, const int* in_sizes, int n_in,
                              void* d_out, int out_size) {
    const float* x = (const float*)d_in[0];
    const float* w = (const float*)d_in[1];
    const float* bias = (const float*)d_in[2];
    float* out = (float*)d_out;

    init_kernel<<<1, 32>>>();
    amax_fused_kernel<<<XB + WB, 256>>>(x, w);
    quant_fused_kernel<<<QXB + QWB, 256>>>(x, w);

    cudaFuncSetAttribute(gemm_kernel,
                         cudaFuncAttributeMaxDynamicSharedMemorySize, GEMM_SMEM);
    gemm_kernel<<<dim3(NT / 128, MT / BM), 256, GEMM_SMEM>>>(out, bias);
}

// round 17
// speedup vs baseline: 1.0607x; 1.0507x over previous
#include <cuda_runtime.h>
#include <cstdint>
#include <cstddef>

// ---------------------------------------------------------------------------
// out = fq(x) @ fq(W)^T + bias, fq = per-tensor symmetric int8 fake quant.
// Exact: out = (q_x @ q_w^T) * (s_x*s_w) + bias, int32 accumulation.
//
// R16: R15 fused hybrid (every warp: IMMA cols [0,96) + dp4a cols [96,128))
// with the dp4a work INTERLEAVED into the ks loop. R15 issued all 48 MMAs
// then all 512 dp4a per warp per kc; lockstep warps -> tensor idled through
// the collective dp4a tail (tensor busy 84.4%). Now each ks-step issues
// 12 MMAs (~670cyc tensor backlog) then 2 dp4a chunks, shrinking idle
// windows 4x; warp stagger hides the rest.
// ---------------------------------------------------------------------------

#define MT 16384
#define NT 4096
#define KT 4096

__device__ __align__(1024) int8_t g_qx[(size_t)MT * KT]; // 64 MiB scratch
__device__ __align__(1024) int8_t g_qw[(size_t)NT * KT]; // 16 MiB scratch
__device__ unsigned g_amax_x;
__device__ unsigned g_amax_w;

__device__ __forceinline__ uint32_t smem_to_u32(const void* smem_ptr) {
    uint32_t addr;
    asm("{ .reg .u64 tmp; cvta.to.shared.u64 tmp, %1; cvt.u32.u64 %0, tmp; }"
        : "=r"(addr) : "l"(smem_ptr));
    return addr;
}

// ---------------------------------------------------------------------------
// Pass 0: reset reduction state
// ---------------------------------------------------------------------------
__global__ void init_kernel() {
    if (threadIdx.x == 0) { g_amax_x = 0u; g_amax_w = 0u; }
}

// ---------------------------------------------------------------------------
// Pass 1 (fused): abs-max of x (blocks [0,XB)) and w (blocks [XB,XB+WB))
// ---------------------------------------------------------------------------
#define XB 2048
#define WB 512
__global__ void amax_fused_kernel(const float* __restrict__ x,
                                  const float* __restrict__ w) {
    __shared__ float red[8];
    int isw = (blockIdx.x >= XB);
    const float4* p4 = (const float4*)(isw ? w : x);
    int n4 = isw ? (NT * KT / 4) : (MT * KT / 4);
    int nb = isw ? WB : XB;
    int bid = isw ? (blockIdx.x - XB) : blockIdx.x;

    float m = 0.f;
    int stride = nb * blockDim.x;
    for (int i = bid * blockDim.x + threadIdx.x; i < n4; i += stride) {
        float4 v = p4[i];
        m = fmaxf(m, fmaxf(fmaxf(fabsf(v.x), fabsf(v.y)),
                           fmaxf(fabsf(v.z), fabsf(v.w))));
    }
    #pragma unroll
    for (int o = 16; o; o >>= 1) m = fmaxf(m, __shfl_xor_sync(0xffffffffu, m, o));
    if ((threadIdx.x & 31) == 0) red[threadIdx.x >> 5] = m;
    __syncthreads();
    if (threadIdx.x == 0) {
        float mm = red[0];
        for (int j = 1; j < (int)(blockDim.x >> 5); j++) mm = fmaxf(mm, red[j]);
        atomicMax(isw ? &g_amax_w : &g_amax_x, __float_as_uint(mm));
    }
}

// ---------------------------------------------------------------------------
// Pass 2 (fused): quantize x and w to int8
// ---------------------------------------------------------------------------
#define QXB 4096
#define QWB 1024
__device__ __forceinline__ int q1(float v, float inv_scale) {
    int q = __float2int_rn(v * inv_scale);   // round-half-even like jnp.round
    return max(-127, min(127, q));
}

__global__ void quant_fused_kernel(const float* __restrict__ x,
                                   const float* __restrict__ w) {
    int isw = (blockIdx.x >= QXB);
    float scale = fmaxf(__uint_as_float(isw ? g_amax_w : g_amax_x) * (1.f / 127.f),
                        1e-8f);
    float inv = 1.f / scale;
    const float4* in4 = (const float4*)(isw ? w : x);
    uint32_t* o4 = isw ? (uint32_t*)g_qw : (uint32_t*)g_qx;
    int n4 = isw ? (NT * KT / 4) : (MT * KT / 4);
    int nb = isw ? QWB : QXB;
    int bid = isw ? (blockIdx.x - QXB) : blockIdx.x;

    int stride = nb * blockDim.x;
    for (int i = bid * blockDim.x + threadIdx.x; i < n4; i += stride) {
        float4 v = in4[i];
        uint32_t u = (uint32_t)(q1(v.x, inv) & 0xff)
                   | ((uint32_t)(q1(v.y, inv) & 0xff) << 8)
                   | ((uint32_t)(q1(v.z, inv) & 0xff) << 16)
                   | ((uint32_t)(q1(v.w, inv) & 0xff) << 24);
        o4[i] = u;
    }
}

// ---------------------------------------------------------------------------
// Pass 3: fused-hybrid GEMM. Tile 128x128x128, 256 threads, 3-stage cp.async.
//   stage: A[128x128B] swz128 | B_imma[96x128B] swz128 | B_dp[32x128B] swzcol
// ---------------------------------------------------------------------------
#define BM 128
#define BK 128
#define STAGES 3
#define NITER (KT / BK)                  // 32
#define ASZ (BM * BK)                    // 16384 B
#define BSZI (96 * BK)                   // 12288 B
#define BSZD (32 * BK)                   // 4096 B
#define STAGE_BYTES (ASZ + BSZI + BSZD)  // 32768 B
#define GEMM_SMEM (STAGES * STAGE_BYTES) // 98304 B

// ldmatrix-compatible swizzle: 128B rows, chunk' = chunk ^ (row&7)
__device__ __forceinline__ uint32_t swz128(uint32_t row, uint32_t c) {
    return row * 128u + ((c ^ (row & 7u)) << 4);
}

#define CP16(dst, src) \
    asm volatile("cp.async.cg.shared.global [%0], [%1], 16;" :: "r"(dst), "l"(src))
#define CP_COMMIT() asm volatile("cp.async.commit_group;" ::: "memory")
#define CP_WAIT(n)  asm volatile("cp.async.wait_group %0;" :: "n"(n) : "memory")

#define LDSM_X4(r0, r1, r2, r3, a) \
    asm volatile("ldmatrix.sync.aligned.m8n8.x4.shared.b16 {%0,%1,%2,%3}, [%4];" \
        : "=r"(r0), "=r"(r1), "=r"(r2), "=r"(r3) : "r"(a))

#define MMA_S8(c, a, b0, b1) \
    asm volatile("mma.sync.aligned.m16n8k32.row.col.s32.s8.s8.s32 " \
        "{%0,%1,%2,%3}, {%4,%5,%6,%7}, {%8,%9}, {%0,%1,%2,%3};" \
        : "+r"((c)[0]), "+r"((c)[1]), "+r"((c)[2]), "+r"((c)[3]) \
        : "r"((a)[0]), "r"((a)[1]), "r"((a)[2]), "r"((a)[3]), "r"(b0), "r"(b1))

__global__ void __launch_bounds__(256, 2)
gemm_kernel(float* __restrict__ out, const float* __restrict__ bias) {
    extern __shared__ char smem[];
    uint32_t sb = smem_to_u32(smem);
    int tid = threadIdx.x, lane = tid & 31, w = tid >> 5;
    int mtile = blockIdx.y;
    int ncol0 = blockIdx.x * 128;

    // ---- loader mapping (all 256 threads): r0 in 0..31, chunk cc in 0..7 ---
    int r0 = tid >> 3, cc = tid & 7;
    const int8_t* gA  = g_qx + ((size_t)(mtile * BM + r0)) * KT + cc * 16;
    const int8_t* gBi = g_qw + ((size_t)(ncol0 + r0)) * KT + cc * 16;
    const int8_t* gBd = g_qw + ((size_t)(ncol0 + 96 + r0)) * KT + cc * 16;
    uint32_t dA  = swz128((uint32_t)r0, (uint32_t)cc);   // also valid +32it rows
    uint32_t phr = (uint32_t)((r0 ^ (r0 >> 2)) & 7);
    uint32_t dBd = (uint32_t)(ASZ + BSZI) + (uint32_t)r0 * 128u
                 + (((uint32_t)cc ^ phr) << 4);

    float sx = fmaxf(__uint_as_float(g_amax_x) * (1.f / 127.f), 1e-8f);
    float sw = fmaxf(__uint_as_float(g_amax_w) * (1.f / 127.f), 1e-8f);
    float sc = sx * sw;

    // ---- IMMA role: 4x2 warp grid over 128x96 ------------------------------
    int wm = w & 3, wn = w >> 2;       // wm rows*32, wn cols*48
    uint32_t a_row = (uint32_t)(wm * 32 + ((lane >> 3) & 1) * 8 + (lane & 7));
    uint32_t a_cb  = (uint32_t)((lane >> 4) & 1);
    uint32_t aoff[2];
    #pragma unroll
    for (int mt = 0; mt < 2; mt++) aoff[mt] = swz128(a_row + mt * 16, a_cb);

    uint32_t b_row = (uint32_t)(wn * 48 + ((lane >> 4) & 1) * 8 + (lane & 7));
    uint32_t b_cb  = (uint32_t)((lane >> 3) & 1);
    uint32_t boff[3];
    #pragma unroll
    for (int p = 0; p < 3; p++) boff[p] = swz128(b_row + p * 16, b_cb);

    int acc[2][6][4];
    #pragma unroll
    for (int i = 0; i < 2; i++)
        #pragma unroll
        for (int j = 0; j < 6; j++)
            #pragma unroll
            for (int k = 0; k < 4; k++) acc[i][j][k] = 0;

    // ---- dp4a role: thread tile 4 rows (stride 32) x 4 cols ---------------
    // rows: r0 + 32i; cols: 96 + cc*4 + j.  A reads reuse swz128 A tile
    // (rows 32 apart share phase r0&7 -> 4 distinct phases per warp).
    uint32_t abase[4];
    #pragma unroll
    for (int i = 0; i < 4; i++)
        abase[i] = (uint32_t)(r0 + 32 * i) * 128u + (((uint32_t)r0 & 7u) << 4);
    uint32_t bbase[4];
    #pragma unroll
    for (int j = 0; j < 4; j++) {
        uint32_t col = (uint32_t)(cc * 4 + j);
        uint32_t ph = (col ^ (col >> 2)) & 7u;
        bbase[j] = (uint32_t)(ASZ + BSZI) + col * 128u + (ph << 4);
    }
    int acc_d[4][4];
    #pragma unroll
    for (int i = 0; i < 4; i++)
        #pragma unroll
        for (int j = 0; j < 4; j++) acc_d[i][j] = 0;

    // ---- prologue: stages 0..STAGES-2 -------------------------------------
    #pragma unroll
    for (int s = 0; s < STAGES - 1; s++) {
        uint32_t st = sb + (uint32_t)s * STAGE_BYTES;
        #pragma unroll
        for (int it = 0; it < 4; it++)
            CP16(st + dA + it * 4096u, gA + (size_t)it * 32 * KT + s * BK);
        #pragma unroll
        for (int it = 0; it < 3; it++)
            CP16(st + ASZ + dA + it * 4096u, gBi + (size_t)it * 32 * KT + s * BK);
        CP16(st + dBd, gBd + s * BK);
        CP_COMMIT();
    }

    for (int kc = 0; kc < NITER; kc++) {
        CP_WAIT(STAGES - 2);
        __syncthreads();

        int lc = kc + STAGES - 1;
        if (lc < NITER) {
            uint32_t st = sb + (uint32_t)(lc % STAGES) * STAGE_BYTES;
            #pragma unroll
            for (int it = 0; it < 4; it++)
                CP16(st + dA + it * 4096u, gA + (size_t)it * 32 * KT + lc * BK);
            #pragma unroll
            for (int it = 0; it < 3; it++)
                CP16(st + ASZ + dA + it * 4096u,
                     gBi + (size_t)it * 32 * KT + lc * BK);
            CP16(st + dBd, gBd + lc * BK);
        }
        CP_COMMIT();

        uint32_t sA = sb + (uint32_t)(kc % STAGES) * STAGE_BYTES;
        uint32_t sB = sA + ASZ;
        const char* pst = smem + (size_t)(kc % STAGES) * STAGE_BYTES;

        // ---- interleaved: per ks-step, 12 MMAs then 2 dp4a chunks ---------
        #pragma unroll
        for (int ks = 0; ks < 4; ks++) {
            uint32_t x = (uint32_t)ks << 5;
            uint32_t afr[2][4], bfr[3][4];
            #pragma unroll
            for (int mt = 0; mt < 2; mt++)
                LDSM_X4(afr[mt][0], afr[mt][1], afr[mt][2], afr[mt][3],
                        sA + (aoff[mt] ^ x));
            #pragma unroll
            for (int p = 0; p < 3; p++)
                LDSM_X4(bfr[p][0], bfr[p][1], bfr[p][2], bfr[p][3],
                        sB + (boff[p] ^ x));
            #pragma unroll
            for (int mt = 0; mt < 2; mt++)
                #pragma unroll
                for (int nt = 0; nt < 6; nt++)
                    MMA_S8(acc[mt][nt], afr[mt],
                           bfr[nt >> 1][(nt & 1) * 2],
                           bfr[nt >> 1][(nt & 1) * 2 + 1]);

            // dp4a chunks c = 2*ks, 2*ks+1 (issued while tensor pipe drains)
            #pragma unroll
            for (int cq = 0; cq < 2; cq++) {
                uint32_t cx = (uint32_t)(ks * 2 + cq) << 4;
                uint4 a4[4];
                #pragma unroll
                for (int i = 0; i < 4; i++)
                    a4[i] = *(const uint4*)(pst + (abase[i] ^ cx));
                #pragma unroll
                for (int j = 0; j < 4; j++) {
                    uint4 b4 = *(const uint4*)(pst + (bbase[j] ^ cx));
                    #pragma unroll
                    for (int i = 0; i < 4; i++) {
                        acc_d[i][j] = __dp4a((int)a4[i].x, (int)b4.x, acc_d[i][j]);
                        acc_d[i][j] = __dp4a((int)a4[i].y, (int)b4.y, acc_d[i][j]);
                        acc_d[i][j] = __dp4a((int)a4[i].z, (int)b4.z, acc_d[i][j]);
                        acc_d[i][j] = __dp4a((int)a4[i].w, (int)b4.w, acc_d[i][j]);
                    }
                }
            }
        }
    }

    // ---- IMMA epilogue: cols [ncol0, ncol0+96) ----------------------------
    {
        int colbase = ncol0 + wn * 48 + 2 * (lane & 3);
        int rowbase = mtile * BM + wm * 32 + (lane >> 2);
        float2 bv[6];
        #pragma unroll
        for (int nt = 0; nt < 6; nt++)
            bv[nt] = *reinterpret_cast<const float2*>(bias + colbase + nt * 8);
        #pragma unroll
        for (int mt = 0; mt < 2; mt++) {
            int r = rowbase + mt * 16;
            #pragma unroll
            for (int nt = 0; nt < 6; nt++) {
                int col = colbase + nt * 8;
                float2 v0, v1;
                v0.x = fmaf((float)acc[mt][nt][0], sc, bv[nt].x);
                v0.y = fmaf((float)acc[mt][nt][1], sc, bv[nt].y);
                v1.x = fmaf((float)acc[mt][nt][2], sc, bv[nt].x);
                v1.y = fmaf((float)acc[mt][nt][3], sc, bv[nt].y);
                *reinterpret_cast<float2*>(out + (size_t)r * NT + col) = v0;
                *reinterpret_cast<float2*>(out + (size_t)(r + 8) * NT + col) = v1;
            }
        }
    }

    // ---- dp4a epilogue: cols [ncol0+96, ncol0+128) ------------------------
    {
        int gcol = ncol0 + 96 + cc * 4;
        float4 bv = *reinterpret_cast<const float4*>(bias + gcol);
        #pragma unroll
        for (int i = 0; i < 4; i++) {
            int grow = mtile * BM + r0 + 32 * i;
            float4 v;
            v.x = fmaf((float)acc_d[i][0], sc, bv.x);
            v.y = fmaf((float)acc_d[i][1], sc, bv.y);
            v.z = fmaf((float)acc_d[i][2], sc, bv.z);
            v.w = fmaf((float)acc_d[i][3], sc, bv.w);
            *reinterpret_cast<float4*>(out + (size_t)grow * NT + gcol) = v;
        }
    }
}

// ---------------------------------------------------------------------------
// Launch (graph-capturable; no allocation, no sync)
// ---------------------------------------------------------------------------
extern "C" void kernel_launch(void* const* d_in, const int* in_sizes, int n_in,
                              void* d_out, int out_size) {
    const float* x = (const float*)d_in[0];
    const float* w = (const float*)d_in[1];
    const float* bias = (const float*)d_in[2];
    float* out = (float*)d_out;

    init_kernel<<<1, 32>>>();
    amax_fused_kernel<<<XB + WB, 256>>>(x, w);
    quant_fused_kernel<<<QXB + QWB, 256>>>(x, w);

    cudaFuncSetAttribute(gemm_kernel,
                         cudaFuncAttributeMaxDynamicSharedMemorySize, GEMM_SMEM);
    gemm_kernel<<<dim3(NT / 128, MT / BM), 256, GEMM_SMEM>>>(out, bias);
}